// round 1
// baseline (speedup 1.0000x reference)
#include <cuda_runtime.h>
#include <math.h>

#define NCLS   1000
#define NROWS  65536
#define EPSF   1e-6f
#define WARPS_PER_BLK 8
#define THREADS 256

// Global accumulators (device globals: no allocation allowed)
__device__ double g_S3;        // sum over unlabeled rows of sum_c -log(1-soft+eps)*idx[c]
__device__ double g_S2;        // sum over labeled rows of pu2 per-row term
__device__ double g_CE;        // sum over labeled rows of -logsoftmax[lab]
__device__ double g_sumPrior;  // sum of priorlist
__device__ unsigned long long g_nP;
__device__ float  g_C0;        // logf(1+eps)
__device__ float  g_idxf[1024];

// ---------------------------------------------------------------------------
__global__ void init_kernel(const float* __restrict__ prior,
                            const int* __restrict__ indexlist) {
    __shared__ double red[32];
    int t = threadIdx.x;  // blockDim = 1024
    if (t == 0) {
        g_S3 = 0.0; g_S2 = 0.0; g_CE = 0.0; g_nP = 0ull;
        g_C0 = logf(1.0f + EPSF);
    }
    float idv = 0.0f;
    double pv = 0.0;
    if (t < NCLS) {
        idv = (float)indexlist[t];
        pv  = (double)prior[t];
    }
    g_idxf[t] = idv;
    #pragma unroll
    for (int o = 16; o; o >>= 1) pv += __shfl_xor_sync(0xffffffffu, pv, o);
    if ((t & 31) == 0) red[t >> 5] = pv;
    __syncthreads();
    if (t < 32) {
        double v = red[t];
        #pragma unroll
        for (int o = 16; o; o >>= 1) v += __shfl_xor_sync(0xffffffffu, v, o);
        if (t == 0) g_sumPrior = v;
    }
}

// ---------------------------------------------------------------------------
// One row (1000 fp32) per warp; each lane holds 8 float4 = 32 elements.
__global__ __launch_bounds__(THREADS)
void mpuloss_main(const float* __restrict__ outputs,
                  const int*   __restrict__ labels,
                  const float* __restrict__ prior) {
    __shared__ float  s_idx[1000];
    __shared__ double sh3[WARPS_PER_BLK], sh2[WARPS_PER_BLK], shc[WARPS_PER_BLK];
    __shared__ int    shn[WARPS_PER_BLK];

    const int tid = threadIdx.x;
    for (int i = tid; i < 1000; i += THREADS) s_idx[i] = g_idxf[i];
    __syncthreads();

    const int warp = tid >> 5;
    const int lane = tid & 31;
    const int row  = blockIdx.x * WARPS_PER_BLK + warp;
    const float* xrow = outputs + (size_t)row * NCLS;

    const int  lab     = labels[row];
    const bool labeled = (lab <= NCLS - 1);

    // ---- load full row into registers (250 float4, MLP=8 per lane) ----
    float4 v[8];
    #pragma unroll
    for (int i = 0; i < 8; i++) {
        const int q = i * 32 + lane;           // float4 index
        if (q < 250) {
            v[i] = reinterpret_cast<const float4*>(xrow)[q];
        } else {
            v[i] = make_float4(-INFINITY, -INFINITY, -INFINITY, -INFINITY);
        }
    }

    // ---- row max ----
    float mx = -INFINITY;
    #pragma unroll
    for (int i = 0; i < 8; i++)
        mx = fmaxf(mx, fmaxf(fmaxf(v[i].x, v[i].y), fmaxf(v[i].z, v[i].w)));

    // capture x[lab] before overwriting registers
    float xlab = 0.0f;
    if (labeled) {
        const int ql = lab >> 2;
        #pragma unroll
        for (int i = 0; i < 8; i++) {
            const int q = i * 32 + lane;
            if (q == ql) {
                float c = (lab & 2) ? ((lab & 1) ? v[i].w : v[i].z)
                                    : ((lab & 1) ? v[i].y : v[i].x);
                xlab = c;
            }
        }
    }

    #pragma unroll
    for (int o = 16; o; o >>= 1) mx = fmaxf(mx, __shfl_xor_sync(0xffffffffu, mx, o));
    #pragma unroll
    for (int o = 16; o; o >>= 1) xlab += __shfl_xor_sync(0xffffffffu, xlab, o);

    // ---- exp pass (overwrite v with e = exp(x - mx)) + Z ----
    const float L2E = 1.4426950408889634f;
    float z = 0.0f;
    #pragma unroll
    for (int i = 0; i < 8; i++) {
        const int q = i * 32 + lane;
        if (q < 250) {
            v[i].x = exp2f((v[i].x - mx) * L2E);
            v[i].y = exp2f((v[i].y - mx) * L2E);
            v[i].z = exp2f((v[i].z - mx) * L2E);
            v[i].w = exp2f((v[i].w - mx) * L2E);
            z += (v[i].x + v[i].y) + (v[i].z + v[i].w);
        }
    }
    #pragma unroll
    for (int o = 16; o; o >>= 1) z += __shfl_xor_sync(0xffffffffu, z, o);

    double wS3 = 0.0, wS2 = 0.0, wCE = 0.0;

    if (!labeled) {
        // pu3 term: sum_c -log(1 - soft + eps) * idx[c]
        const float invZ = 1.0f / z;
        float acc = 0.0f;
        #pragma unroll
        for (int i = 0; i < 8; i++) {
            const int q = i * 32 + lane;
            if (q < 250) {
                const float4 id = *reinterpret_cast<const float4*>(&s_idx[q * 4]);
                float s, u;
                s = v[i].x * invZ; u = (1.0f - s) + EPSF; acc = fmaf(id.x, -__logf(u), acc);
                s = v[i].y * invZ; u = (1.0f - s) + EPSF; acc = fmaf(id.y, -__logf(u), acc);
                s = v[i].z * invZ; u = (1.0f - s) + EPSF; acc = fmaf(id.z, -__logf(u), acc);
                s = v[i].w * invZ; u = (1.0f - s) + EPSF; acc = fmaf(id.w, -__logf(u), acc);
            }
        }
        #pragma unroll
        for (int o = 16; o; o >>= 1) acc += __shfl_xor_sync(0xffffffffu, acc, o);
        if (lane == 0) wS3 = (double)acc;
    } else if (lane == 0) {
        // pu2 per-row: C0*(sumPrior - prior[lab]) + log(1 - soft[lab] + eps)*prior[lab]
        const float elab = exp2f((xlab - mx) * L2E);
        const float slab = elab / z;
        const float p    = prior[lab];
        const float r2   = g_C0 * ((float)g_sumPrior - p)
                         + logf((1.0f - slab) + EPSF) * p;
        // cross entropy: -(x[lab] - mx - log Z)
        const float ce = -(xlab - mx - __logf(z));
        wS2 = (double)r2;
        wCE = (double)ce;
    }

    if (lane == 0) {
        sh3[warp] = wS3; sh2[warp] = wS2; shc[warp] = wCE;
        shn[warp] = labeled ? 1 : 0;
    }
    __syncthreads();
    if (tid == 0) {
        double a = 0.0, b = 0.0, c = 0.0; int n = 0;
        #pragma unroll
        for (int i = 0; i < WARPS_PER_BLK; i++) {
            a += sh3[i]; b += sh2[i]; c += shc[i]; n += shn[i];
        }
        atomicAdd(&g_S3, a);
        atomicAdd(&g_S2, b);
        atomicAdd(&g_CE, c);
        atomicAdd(&g_nP, (unsigned long long)n);
    }
}

// ---------------------------------------------------------------------------
__global__ void finalize_kernel(float* out, int out_size) {
    const double nP = (double)g_nP;
    const double nU = (double)NROWS - nP;
    const double pu3 = g_S3 / fmax(1.0, nU) / (double)NCLS;
    const double pu2 = g_S2 / fmax(1.0, nP);
    const double PULoss  = pu3 + pu2;
    const double PULossW = PULoss * 2.0;

    float cross, obj;
    if (g_nP > 0ull) {
        cross = (float)(g_CE / nP);
        obj   = (float)(PULossW + (double)cross);
    } else {
        cross = __int_as_float(0x7fc00000);  // nan, matching 0/0
        obj   = (float)PULoss;               // reference picks unweighted PULoss
    }
    if (out_size >= 1) out[0] = obj;
    if (out_size >= 2) out[1] = (float)PULossW;
    if (out_size >= 3) out[2] = cross;
}

// ---------------------------------------------------------------------------
extern "C" void kernel_launch(void* const* d_in, const int* in_sizes, int n_in,
                              void* d_out, int out_size) {
    const float* outputs   = (const float*)d_in[0];
    const int*   labels    = (const int*)d_in[1];
    const float* prior     = (const float*)d_in[2];
    const int*   indexlist = (const int*)d_in[3];

    init_kernel<<<1, 1024>>>(prior, indexlist);
    mpuloss_main<<<NROWS / WARPS_PER_BLK, THREADS>>>(outputs, labels, prior);
    finalize_kernel<<<1, 1>>>((float*)d_out, out_size);
}